// round 8
// baseline (speedup 1.0000x reference)
#include <cuda_runtime.h>
#include <math.h>

// Problem constants
#define NQ   64          // queries
#define DD   256         // feature dim
#define NS   4096        // bank size
#define IMG  65536       // C*H*W floats per image
#define FPB  32          // features per sim block
#define SIMBLOCKS (NS / FPB)   // 128

// smem layout for sim kernel (transposed, padded strides)
#define QS_STRIDE 68     // 64 rows + 4 pad (float4-aligned reads, conflict-free)
#define FS_STRIDE 36     // 32 rows + 4 pad
#define QS_FLOATS (DD * QS_STRIDE)   // 17408
#define FS_FLOATS (DD * FS_STRIDE)   //  9216
#define RED_SLOTS (NQ * 16)          // per-(query, ty) partials
#define SMEM_BYTES ((QS_FLOATS + FS_FLOATS) * 4 + RED_SLOTS * 8)  // 114688 B

// Gather: 16 KB chunk per block, moved by TMA bulk copy through smem.
#define CHUNK_BYTES 16384
#define CHUNK_FLOATS (CHUNK_BYTES / 4)       // 4096
#define NCHUNK (IMG / CHUNK_FLOATS)          // 16

// Per-(query, sim-block) partial argmax results. Every slot is rewritten on
// every replay -> no reset kernel, no atomics, fully deterministic.
__device__ unsigned long long g_part[NQ * SIMBLOCKS];

__device__ __forceinline__ unsigned long long packkey(float f, unsigned idx) {
    unsigned u = __float_as_uint(f);
    u = (u & 0x80000000u) ? ~u : (u | 0x80000000u);
    return ((unsigned long long)u << 32) | (0xFFFFFFFFu - idx);
}
__device__ __forceinline__ float unpackscore(unsigned long long p) {
    unsigned u = (unsigned)(p >> 32);
    unsigned bits = (u & 0x80000000u) ? (u & 0x7FFFFFFFu) : ~u;
    return __uint_as_float(bits);
}
__device__ __forceinline__ unsigned long long umax64(unsigned long long a,
                                                     unsigned long long b) {
    return a > b ? a : b;
}
__device__ __forceinline__ unsigned smem_u32(const void* p) {
    unsigned a;
    asm("{ .reg .u64 t; cvta.to.shared.u64 t, %1; cvt.u32.u64 %0, t; }"
        : "=r"(a) : "l"(p));
    return a;
}

// ---------------------------------------------------------------------------
// Kernel 1: sim tile GEMM (64 q x 32 f x K=256) on RAW q + fused argmax.
// argmax(q.F^T) == argmax(q_hat.F^T) since 1/||q|| > 0; norm applied at
// score-write time. 256 threads (8 warps = 2/SMSP), thread tile 4x2.
// Staging uses a 4-rows x 8-ks lane remap -> conflict-free transposed stores.
// ---------------------------------------------------------------------------
__global__ void __launch_bounds__(256, 1) sim_kernel(const float* __restrict__ q,
                                                     const float* __restrict__ feats) {
    extern __shared__ float sm[];
    float* qs = sm;                          // [256][68]  qs[k*68 + qrow]
    float* fs = sm + QS_FLOATS;              // [256][36]  fs[k*36 + frow]
    unsigned long long* red =
        (unsigned long long*)(sm + QS_FLOATS + FS_FLOATS);   // [64][16]

    const int tid  = threadIdx.x;
    const int lane = tid & 31;
    const int warp = tid >> 5;               // 8 warps
    const int f0   = blockIdx.x * FPB;

    const int dr = lane >> 3;                // 0..3  row within 4-row group
    const int dk = lane & 7;                 // 0..7  k within 8-k group

    // Stage raw q transposed: 512 groups of (4 rows x 8 ks), 64 per warp.
    #pragma unroll 4
    for (int g = warp; g < 512; g += 8) {
        int rb = g & 15, kb = g >> 4;        // 16 row-blocks x 32 k-blocks
        int r = rb * 4 + dr, k = kb * 8 + dk;
        qs[k * QS_STRIDE + r] = q[r * DD + k];
    }
    // Stage this block's 32 feature rows transposed: 256 groups, 32 per warp.
    #pragma unroll 4
    for (int g = warp; g < 256; g += 8) {
        int rb = g & 7, kb = g >> 3;         // 8 row-blocks x 32 k-blocks
        int r = rb * 4 + dr, k = kb * 8 + dk;
        fs[k * FS_STRIDE + r] = feats[(size_t)(f0 + r) * DD + k];
    }
    __syncthreads();

    const int tx = tid & 15;                 // q rows 4tx..4tx+3
    const int ty = tid >> 4;                 // f cols 2ty, 2ty+1
    float acc[4][2];
    #pragma unroll
    for (int i = 0; i < 4; i++) { acc[i][0] = 0.f; acc[i][1] = 0.f; }

    #pragma unroll 8
    for (int k = 0; k < DD; k++) {
        float4 a = *reinterpret_cast<const float4*>(&qs[k * QS_STRIDE + 4 * tx]);
        float2 b = *reinterpret_cast<const float2*>(&fs[k * FS_STRIDE + 2 * ty]);
        float av[4] = {a.x, a.y, a.z, a.w};
        #pragma unroll
        for (int i = 0; i < 4; i++) {
            acc[i][0] = fmaf(av[i], b.x, acc[i][0]);
            acc[i][1] = fmaf(av[i], b.y, acc[i][1]);
        }
    }

    // Per-thread max over its 2 features (strict > keeps lowest index on tie)
    #pragma unroll
    for (int i = 0; i < 4; i++) {
        float m = acc[i][0]; int bj = 0;
        if (acc[i][1] > m) { m = acc[i][1]; bj = 1; }
        red[(4 * tx + i) * 16 + ty] = packkey(m, (unsigned)(f0 + 2 * ty + bj));
    }
    __syncthreads();

    // One thread per query reduces the 16 ty-partials -> its private slot.
    if (tid < NQ) {
        unsigned long long p = red[tid * 16];
        #pragma unroll
        for (int j = 1; j < 16; j++) p = umax64(p, red[tid * 16 + j]);
        g_part[tid * SIMBLOCKS + blockIdx.x] = p;
    }
}

// ---------------------------------------------------------------------------
// Kernel 2: per-query final argmax reduce (redundant per block, L2-hot 1 KB)
// + image gather via TMA bulk copy (global -> smem -> global, 16 KB/block)
// + normalized score write. Grid (16 chunks, 64 queries) x 128 threads.
// TMA sidesteps the cross-CTA L1tex wavefront-queue contention that capped
// the LDG/STG version at ~22% DRAM.
// ---------------------------------------------------------------------------
__global__ void __launch_bounds__(128) gather_kernel(const float* __restrict__ q,
                                                     const float* __restrict__ images,
                                                     float* __restrict__ out) {
    __shared__ alignas(128) float buf[CHUNK_FLOATS];
    __shared__ alignas(8) unsigned long long mbar;
    __shared__ unsigned long long sred[4];
    __shared__ unsigned long long sbest;

    const int qi = blockIdx.y;
    const int t  = threadIdx.x;
    const unsigned mb = smem_u32(&mbar);

    if (t == 0)
        asm volatile("mbarrier.init.shared.b64 [%0], 1;" :: "r"(mb) : "memory");

    // Reduce 128 per-block partials for this query (all 128 threads).
    unsigned long long p = g_part[qi * SIMBLOCKS + t];
    #pragma unroll
    for (int o = 16; o; o >>= 1)
        p = umax64(p, __shfl_xor_sync(0xffffffffu, p, o));
    if ((t & 31) == 0) sred[t >> 5] = p;
    __syncthreads();   // also orders mbarrier.init before use
    if (t == 0) {
        unsigned long long m = sred[0];
        #pragma unroll
        for (int j = 1; j < 4; j++) m = umax64(m, sred[j]);
        sbest = m;

        const unsigned idx = 0xFFFFFFFFu - (unsigned)(m & 0xFFFFFFFFu);
        const float* src = images + (size_t)idx * IMG
                           + (size_t)blockIdx.x * CHUNK_FLOATS;
        float* dst = out + (size_t)qi * IMG + (size_t)blockIdx.x * CHUNK_FLOATS;
        const unsigned sb = smem_u32(buf);

        // Bulk load global -> smem, completion via mbarrier transaction count.
        asm volatile("mbarrier.arrive.expect_tx.shared.b64 _, [%0], %1;"
                     :: "r"(mb), "r"((unsigned)CHUNK_BYTES) : "memory");
        asm volatile(
            "cp.async.bulk.shared::cta.global.mbarrier::complete_tx::bytes "
            "[%0], [%1], %2, [%3];"
            :: "r"(sb), "l"(src), "r"((unsigned)CHUNK_BYTES), "r"(mb)
            : "memory");

        // Wait (phase 0).
        {
            unsigned done;
            asm volatile(
                "{\n\t.reg .pred p;\n\t"
                "mbarrier.try_wait.parity.acquire.cta.shared::cta.b64 p, [%1], 0;\n\t"
                "selp.b32 %0, 1, 0, p;\n\t}"
                : "=r"(done) : "r"(mb) : "memory");
            if (!done) {
                asm volatile(
                    "{\n\t.reg .pred P1;\n\t"
                    "WL_%=:\n\t"
                    "mbarrier.try_wait.parity.acquire.cta.shared::cta.b64 P1, [%0], 0, 0x989680;\n\t"
                    "@P1 bra.uni WD_%=;\n\t"
                    "bra.uni WL_%=;\n\t"
                    "WD_%=:\n\t}"
                    :: "r"(mb) : "memory");
            }
        }
        asm volatile("fence.proxy.async.shared::cta;" ::: "memory");

        // Bulk store smem -> global; wait before CTA exit so smem stays live.
        asm volatile(
            "cp.async.bulk.global.shared::cta.bulk_group [%0], [%1], %2;"
            :: "l"(dst), "r"(sb), "r"((unsigned)CHUNK_BYTES) : "memory");
        asm volatile("cp.async.bulk.commit_group;" ::: "memory");
        asm volatile("cp.async.bulk.wait_group 0;" ::: "memory");
    }
    __syncthreads();

    // Block (0, qi): compute ||q_qi|| with warp 0 and write normalized score.
    if (blockIdx.x == 0 && t < 32) {
        const float4* qr = reinterpret_cast<const float4*>(q + qi * DD);
        float s = 0.f;
        #pragma unroll
        for (int j = 0; j < 2; j++) {
            float4 w = qr[t + 32 * j];
            s += w.x * w.x + w.y * w.y + w.z * w.z + w.w * w.w;
        }
        #pragma unroll
        for (int o = 16; o; o >>= 1) s += __shfl_xor_sync(0xffffffffu, s, o);
        if (t == 0) {
            float norm = fmaxf(sqrtf(s), 1e-12f);
            out[(size_t)NQ * IMG + qi] = unpackscore(sbest) / norm;
        }
    }
}

// ---------------------------------------------------------------------------
extern "C" void kernel_launch(void* const* d_in, const int* in_sizes, int n_in,
                              void* d_out, int out_size) {
    const float* q      = (const float*)d_in[0];   // (64, 256)
    const float* feats  = (const float*)d_in[1];   // (4096, 256), pre-normalized
    const float* images = (const float*)d_in[2];   // (4096, 1, 256, 256)
    float* out = (float*)d_out;                    // 64*65536 imgs + 64 scores

    cudaFuncSetAttribute(sim_kernel,
                         cudaFuncAttributeMaxDynamicSharedMemorySize, SMEM_BYTES);

    sim_kernel<<<SIMBLOCKS, 256, SMEM_BYTES>>>(q, feats);
    gather_kernel<<<dim3(NCHUNK, NQ), 128>>>(q, images, out);
}